// round 4
// baseline (speedup 1.0000x reference)
#include <cuda_runtime.h>
#include <cuda_bf16.h>
#include <math.h>
#include <cstdint>

#define DIMV    2048
#define SEQ     2048
#define BATCH   2
#define HEADS   16
#define DHEAD   128
#define MROWS   (BATCH*SEQ)   // 4096
#define EPSV    1e-5f

// ---------------- scratch (device globals; no allocation allowed) ----------
__device__ float g_q[(size_t)MROWS * DIMV];
__device__ float g_k[(size_t)MROWS * DIMV];
__device__ float g_v[(size_t)MROWS * DIMV];
__device__ float g_attn[(size_t)MROWS * DIMV];
__device__ __nv_bfloat16 g_ahi[(size_t)MROWS * DIMV];
__device__ __nv_bfloat16 g_alo[(size_t)MROWS * DIMV];
__device__ __nv_bfloat16 g_wqhi[(size_t)DIMV * DIMV];
__device__ __nv_bfloat16 g_wqlo[(size_t)DIMV * DIMV];
__device__ __nv_bfloat16 g_wkhi[(size_t)DIMV * DIMV];
__device__ __nv_bfloat16 g_wklo[(size_t)DIMV * DIMV];
__device__ __nv_bfloat16 g_wvhi[(size_t)DIMV * DIMV];
__device__ __nv_bfloat16 g_wvlo[(size_t)DIMV * DIMV];
__device__ __nv_bfloat16 g_wohi[(size_t)DIMV * DIMV];
__device__ __nv_bfloat16 g_wolo[(size_t)DIMV * DIMV];

// ---------------- arch-neutral tensor helpers (compute_103-safe) -----------
__device__ __forceinline__ uint32_t smem_u32(const void* p) {
    uint32_t a;
    asm("{ .reg .u64 t; cvta.to.shared.u64 t, %1; cvt.u32.u64 %0, t; }"
        : "=r"(a) : "l"(p));
    return a;
}
__device__ __forceinline__ void ldsm4(uint32_t* r, uint32_t addr) {
    asm volatile("ldmatrix.sync.aligned.m8n8.x4.shared.b16 {%0,%1,%2,%3}, [%4];"
                 : "=r"(r[0]), "=r"(r[1]), "=r"(r[2]), "=r"(r[3]) : "r"(addr));
}
__device__ __forceinline__ void mma16816(float* c, const uint32_t* a, const uint32_t* b) {
    asm volatile("mma.sync.aligned.m16n8k16.row.col.f32.bf16.bf16.f32 "
                 "{%0,%1,%2,%3}, {%4,%5,%6,%7}, {%8,%9}, {%0,%1,%2,%3};"
                 : "+f"(c[0]), "+f"(c[1]), "+f"(c[2]), "+f"(c[3])
                 : "r"(a[0]), "r"(a[1]), "r"(a[2]), "r"(a[3]), "r"(b[0]), "r"(b[1]));
}
#define CP_ASYNC16(dst, src) asm volatile("cp.async.cg.shared.global [%0], [%1], 16;" :: "r"(dst), "l"(src))
#define CP_COMMIT()          asm volatile("cp.async.commit_group;" ::: "memory")
#define CP_WAIT1()           asm volatile("cp.async.wait_group 1;" ::: "memory")
#define CP_WAIT0()           asm volatile("cp.async.wait_group 0;" ::: "memory")

// ---------------------------------------------------------------------------
// fp32 -> bf16 hi/lo split (vectorized x4)
// ---------------------------------------------------------------------------
__global__ __launch_bounds__(256)
void split_kernel(const float* __restrict__ x, __nv_bfloat16* __restrict__ hi,
                  __nv_bfloat16* __restrict__ lo, int n)
{
    int i = (blockIdx.x * blockDim.x + threadIdx.x) * 4;
    if (i >= n) return;
    float4 v = *(const float4*)(x + i);
    __nv_bfloat16 h0 = __float2bfloat16(v.x);
    __nv_bfloat16 h1 = __float2bfloat16(v.y);
    __nv_bfloat16 h2 = __float2bfloat16(v.z);
    __nv_bfloat16 h3 = __float2bfloat16(v.w);
    __nv_bfloat16 l0 = __float2bfloat16(v.x - __bfloat162float(h0));
    __nv_bfloat16 l1 = __float2bfloat16(v.y - __bfloat162float(h1));
    __nv_bfloat16 l2 = __float2bfloat16(v.z - __bfloat162float(h2));
    __nv_bfloat16 l3 = __float2bfloat16(v.w - __bfloat162float(h3));
    *(__nv_bfloat162*)(hi + i)     = __nv_bfloat162(h0, h1);
    *(__nv_bfloat162*)(hi + i + 2) = __nv_bfloat162(h2, h3);
    *(__nv_bfloat162*)(lo + i)     = __nv_bfloat162(l0, l1);
    *(__nv_bfloat162*)(lo + i + 2) = __nv_bfloat162(l2, l3);
}

// ---------------------------------------------------------------------------
// bf16 mma.sync GEMM with 3-term split:
//   C[M=4096, N=2048] = (Ahi+Alo)[M,K] @ (Bhi+Blo)[N,K]^T + bias
// CTA tile 128x128, BK=32, double-buffered cp.async. 8 warps (2x4), warp
// tile 64x32, m16n8k16 frags. Accumulate AhiBhi + AhiBlo + AloBhi.
// ---------------------------------------------------------------------------
#define LDT     40                     // padded row stride in bf16 (80 B)
#define STG_OP  (128 * LDT * 2)        // 10240 B per operand per buffer
#define GEMM_SMEM (STG_OP * 8)         // Ahi/Alo/Bhi/Blo x 2 buffers = 81920 B

__global__ __launch_bounds__(256, 1)
void gemm_mma_kernel(const __nv_bfloat16* __restrict__ Ahi, const __nv_bfloat16* __restrict__ Alo,
                     const __nv_bfloat16* __restrict__ Bhi, const __nv_bfloat16* __restrict__ Blo,
                     const float* __restrict__ bias, float* __restrict__ C)
{
    extern __shared__ __align__(128) char smem[];
    const uint32_t sb = smem_u32(smem);
    // operand bases: [op][buf] ; op: 0=Ahi 1=Alo 2=Bhi 3=Blo
    const uint32_t opb[4] = { sb, sb + 2*STG_OP, sb + 4*STG_OP, sb + 6*STG_OP };

    const int tid  = threadIdx.x;
    const int wid  = tid >> 5;
    const int lane = tid & 31;
    const int wm   = wid >> 2;          // 0..1
    const int wn   = wid & 3;           // 0..3
    const int m0   = blockIdx.y * 128;
    const int n0   = blockIdx.x * 128;

    const __nv_bfloat16* gsrc[4] = { Ahi, Alo, Bhi, Blo };
    const int rowoff[4] = { m0, m0, n0, n0 };

    // ---- stage loader: 2048 x 16B cp.async (8 per thread) ----
    auto load_stage = [&](int k0, int buf) {
#pragma unroll
        for (int j = 0; j < 8; j++) {
            const int i  = tid + j * 256;
            const int op = i >> 9;            // 512 chunks per operand
            const int c  = i & 511;
            const int r  = c >> 2;            // row 0..127
            const int cc = c & 3;             // 16B chunk within row
            const uint32_t dst = opb[op] + buf * STG_OP + r * (LDT * 2) + cc * 16;
            const __nv_bfloat16* src = gsrc[op]
                + (size_t)(rowoff[op] + r) * DIMV + k0 + cc * 8;
            CP_ASYNC16(dst, src);
        }
    };

    float acc[4][4][4];
#pragma unroll
    for (int i = 0; i < 4; i++)
#pragma unroll
        for (int j = 0; j < 4; j++)
#pragma unroll
            for (int t = 0; t < 4; t++) acc[i][j][t] = 0.f;

    // ldmatrix lane-address components
    const int a_row = lane & 15;               // A: rows m.. (two 8-row groups)
    const int a_col = (lane >> 4) << 3;        // k offset 0/8
    const int b_row = ((lane >> 4) << 3) + (lane & 7);  // B: n row within 16
    const int b_col = ((lane >> 3) & 1) << 3;  // k offset 0/8

    load_stage(0, 0);
    CP_COMMIT();

    for (int s = 0; s < 64; s++) {
        const int buf = s & 1;
        if (s + 1 < 64) { load_stage((s + 1) * 32, buf ^ 1); CP_COMMIT(); CP_WAIT1(); }
        else            { CP_WAIT0(); }
        __syncthreads();

        const uint32_t aHi = opb[0] + buf * STG_OP;
        const uint32_t aLo = opb[1] + buf * STG_OP;
        const uint32_t bHi = opb[2] + buf * STG_OP;
        const uint32_t bLo = opb[3] + buf * STG_OP;

#pragma unroll
        for (int kk = 0; kk < 32; kk += 16) {
            uint32_t ah[4][4], al[4][4], bh[4][2], bl[4][2];
#pragma unroll
            for (int i = 0; i < 4; i++) {
                const uint32_t off = ((wm * 64 + i * 16 + a_row) * LDT + kk + a_col) * 2;
                ldsm4(ah[i], aHi + off);
                ldsm4(al[i], aLo + off);
            }
#pragma unroll
            for (int j = 0; j < 2; j++) {   // each x4 covers two n8 tiles
                const uint32_t off = ((wn * 32 + j * 16 + b_row) * LDT + kk + b_col) * 2;
                uint32_t t[4];
                ldsm4(t, bHi + off);
                bh[2*j][0] = t[0]; bh[2*j][1] = t[1];
                bh[2*j+1][0] = t[2]; bh[2*j+1][1] = t[3];
                ldsm4(t, bLo + off);
                bl[2*j][0] = t[0]; bl[2*j][1] = t[1];
                bl[2*j+1][0] = t[2]; bl[2*j+1][1] = t[3];
            }
#pragma unroll
            for (int i = 0; i < 4; i++)
#pragma unroll
                for (int j = 0; j < 4; j++) {
                    mma16816(acc[i][j], ah[i], bh[j]);
                    mma16816(acc[i][j], ah[i], bl[j]);
                    mma16816(acc[i][j], al[i], bh[j]);
                }
        }
        __syncthreads();
    }

    // ---- epilogue: bias + store ----
    const int mw = m0 + wm * 64;
    const int nw = n0 + wn * 32;
    const int ml = lane >> 2;
    const int nl = (lane & 3) * 2;
#pragma unroll
    for (int j = 0; j < 4; j++) {
        const int n = nw + j * 8 + nl;
        const float b0 = bias[n], b1 = bias[n + 1];
#pragma unroll
        for (int i = 0; i < 4; i++) {
            const int m = mw + i * 16 + ml;
            *(float2*)&C[(size_t)m * DIMV + n] =
                make_float2(acc[i][j][0] + b0, acc[i][j][1] + b1);
            *(float2*)&C[(size_t)(m + 8) * DIMV + n] =
                make_float2(acc[i][j][2] + b0, acc[i][j][3] + b1);
        }
    }
}

// ---------------------------------------------------------------------------
// Fused RMSNorm + interleaved RoPE + history-key scaling (unchanged)
// ---------------------------------------------------------------------------
__global__ __launch_bounds__(256)
void normrope_kernel(float* __restrict__ q, float* __restrict__ k,
                     const float* __restrict__ rot,
                     const float* __restrict__ wq, const float* __restrict__ wk,
                     const float* __restrict__ hks, const int* __restrict__ oclp)
{
    const int r   = blockIdx.x;
    const int s   = r & (SEQ - 1);
    const int tid = threadIdx.x;
    float* qrow = q + (size_t)r * DIMV;
    float* krow = k + (size_t)r * DIMV;
    const int base = tid * 8;

    float qa[8], ka[8];
    {
        float4 t0 = *(const float4*)(qrow + base);
        float4 t1 = *(const float4*)(qrow + base + 4);
        qa[0]=t0.x; qa[1]=t0.y; qa[2]=t0.z; qa[3]=t0.w;
        qa[4]=t1.x; qa[5]=t1.y; qa[6]=t1.z; qa[7]=t1.w;
        float4 u0 = *(const float4*)(krow + base);
        float4 u1 = *(const float4*)(krow + base + 4);
        ka[0]=u0.x; ka[1]=u0.y; ka[2]=u0.z; ka[3]=u0.w;
        ka[4]=u1.x; ka[5]=u1.y; ka[6]=u1.z; ka[7]=u1.w;
    }

    float sq = 0.f, sk = 0.f;
#pragma unroll
    for (int i = 0; i < 8; i++) { sq = fmaf(qa[i], qa[i], sq); sk = fmaf(ka[i], ka[i], sk); }

    __shared__ float2 red[256];
    red[tid] = make_float2(sq, sk);
    __syncthreads();
#pragma unroll
    for (int off = 128; off > 0; off >>= 1) {
        if (tid < off) {
            red[tid].x += red[tid + off].x;
            red[tid].y += red[tid + off].y;
        }
        __syncthreads();
    }
    const float rq = rsqrtf(red[0].x * (1.f / DIMV) + EPSV);
    const float rk = rsqrtf(red[0].y * (1.f / DIMV) + EPSV);

    const int  hist    = SEQ - oclp[0];
    const bool is_hist = (s < hist);
    const float* rrow  = rot + (size_t)s * (2 * DHEAD);

    float qo[8], ko[8];
#pragma unroll
    for (int t = 0; t < 4; t++) {
        const int p = (base >> 1) + t;
        const int h = p >> 6;
        const int i = p & 63;
        const float c  = rrow[2*i];
        const float si = rrow[DHEAD + 2*i + 1];
        const int n = base + 2*t;
        float q1 = qa[2*t]     * rq * wq[n];
        float q2 = qa[2*t + 1] * rq * wq[n + 1];
        qo[2*t]     = q1*c - q2*si;
        qo[2*t + 1] = q1*si + q2*c;
        float k1 = ka[2*t]     * rk * wk[n];
        float k2 = ka[2*t + 1] * rk * wk[n + 1];
        float ke  = k1*c - k2*si;
        float kod = k1*si + k2*c;
        if (is_hist) {
            const float sc = 1.f + 9.f / (1.f + __expf(-hks[h]));
            ke *= sc; kod *= sc;
        }
        ko[2*t] = ke; ko[2*t + 1] = kod;
    }
    *(float4*)(qrow + base)     = make_float4(qo[0], qo[1], qo[2], qo[3]);
    *(float4*)(qrow + base + 4) = make_float4(qo[4], qo[5], qo[6], qo[7]);
    *(float4*)(krow + base)     = make_float4(ko[0], ko[1], ko[2], ko[3]);
    *(float4*)(krow + base + 4) = make_float4(ko[4], ko[5], ko[6], ko[7]);
}

// ---------------------------------------------------------------------------
// Flash attention fp32 (unchanged)
// ---------------------------------------------------------------------------
#define BQ  64
#define BKV 64
#define ATT_SMEM ((128*64*2 + 64*64) * sizeof(float))

__global__ __launch_bounds__(256, 2)
void flashattn_kernel(const float* __restrict__ Q, const float* __restrict__ K,
                      const float* __restrict__ V, float* __restrict__ O)
{
    extern __shared__ float smf[];
    float* Qs  = smf;
    float* KVs = smf + 128*64;
    float* Ps  = smf + 2*128*64;

    const int tid = threadIdx.x;
    const int tx  = tid & 15;
    const int ty  = tid >> 4;
    const int bh  = blockIdx.y;
    const int b   = bh >> 4;
    const int h   = bh & 15;
    const int q0  = blockIdx.x * BQ;

    const float* Qb = Q + ((size_t)b * SEQ) * DIMV + (size_t)h * DHEAD;
    const float* Kb = K + ((size_t)b * SEQ) * DIMV + (size_t)h * DHEAD;
    const float* Vb = V + ((size_t)b * SEQ) * DIMV + (size_t)h * DHEAD;

    const int lrow  = tid >> 2;
    const int dpart = (tid & 3) * 32;

    {
        const float* src = Qb + (size_t)(q0 + lrow) * DIMV + dpart;
#pragma unroll
        for (int j = 0; j < 8; j++) {
            float4 v4 = *(const float4*)(src + j*4);
            const int d = dpart + j*4;
            Qs[(d+0)*64 + lrow] = v4.x; Qs[(d+1)*64 + lrow] = v4.y;
            Qs[(d+2)*64 + lrow] = v4.z; Qs[(d+3)*64 + lrow] = v4.w;
        }
    }

    float o[4][8];
#pragma unroll
    for (int i = 0; i < 4; i++)
#pragma unroll
        for (int j = 0; j < 8; j++) o[i][j] = 0.f;
    float mprev[4] = {-INFINITY, -INFINITY, -INFINITY, -INFINITY};
    float l[4]     = {0.f, 0.f, 0.f, 0.f};
    const float SCALE = 0.08838834764831845f;

    for (int kv0 = 0; kv0 < SEQ; kv0 += BKV) {
        __syncthreads();
        {
            const float* src = Kb + (size_t)(kv0 + lrow) * DIMV + dpart;
#pragma unroll
            for (int j = 0; j < 8; j++) {
                float4 v4 = *(const float4*)(src + j*4);
                const int d = dpart + j*4;
                KVs[(d+0)*64 + lrow] = v4.x; KVs[(d+1)*64 + lrow] = v4.y;
                KVs[(d+2)*64 + lrow] = v4.z; KVs[(d+3)*64 + lrow] = v4.w;
            }
        }
        __syncthreads();

        float sacc[4][4];
#pragma unroll
        for (int i = 0; i < 4; i++)
#pragma unroll
            for (int j = 0; j < 4; j++) sacc[i][j] = 0.f;
#pragma unroll 8
        for (int d = 0; d < 128; d++) {
            float4 aq = *(const float4*)&Qs[d*64 + ty*4];
            float4 bk = *(const float4*)&KVs[d*64 + tx*4];
            float a[4] = {aq.x, aq.y, aq.z, aq.w};
            float bb[4] = {bk.x, bk.y, bk.z, bk.w};
#pragma unroll
            for (int i = 0; i < 4; i++)
#pragma unroll
                for (int j = 0; j < 4; j++)
                    sacc[i][j] = fmaf(a[i], bb[j], sacc[i][j]);
        }

#pragma unroll
        for (int i = 0; i < 4; i++) {
            float rmax = -INFINITY;
#pragma unroll
            for (int j = 0; j < 4; j++) { sacc[i][j] *= SCALE; rmax = fmaxf(rmax, sacc[i][j]); }
            rmax = fmaxf(rmax, __shfl_xor_sync(0xffffffffu, rmax, 8));
            rmax = fmaxf(rmax, __shfl_xor_sync(0xffffffffu, rmax, 4));
            rmax = fmaxf(rmax, __shfl_xor_sync(0xffffffffu, rmax, 2));
            rmax = fmaxf(rmax, __shfl_xor_sync(0xffffffffu, rmax, 1));
            const float mnew = fmaxf(mprev[i], rmax);
            float p0 = __expf(sacc[i][0] - mnew);
            float p1 = __expf(sacc[i][1] - mnew);
            float p2 = __expf(sacc[i][2] - mnew);
            float p3 = __expf(sacc[i][3] - mnew);
            float rsum = p0 + p1 + p2 + p3;
            rsum += __shfl_xor_sync(0xffffffffu, rsum, 8);
            rsum += __shfl_xor_sync(0xffffffffu, rsum, 4);
            rsum += __shfl_xor_sync(0xffffffffu, rsum, 2);
            rsum += __shfl_xor_sync(0xffffffffu, rsum, 1);
            const float alpha = __expf(mprev[i] - mnew);
            l[i] = l[i] * alpha + rsum;
            mprev[i] = mnew;
            *(float4*)&Ps[(ty*4 + i)*64 + tx*4] = make_float4(p0, p1, p2, p3);
#pragma unroll
            for (int j = 0; j < 8; j++) o[i][j] *= alpha;
        }
        __syncthreads();

        {
            const float* src = Vb + (size_t)(kv0 + lrow) * DIMV + dpart;
#pragma unroll
            for (int j = 0; j < 8; j++)
                *(float4*)&KVs[lrow*128 + dpart + j*4] = *(const float4*)(src + j*4);
        }
        __syncthreads();

#pragma unroll 4
        for (int kk = 0; kk < BKV; kk++) {
            float a0 = Ps[(ty*4 + 0)*64 + kk];
            float a1 = Ps[(ty*4 + 1)*64 + kk];
            float a2 = Ps[(ty*4 + 2)*64 + kk];
            float a3 = Ps[(ty*4 + 3)*64 + kk];
            float4 b0 = *(const float4*)&KVs[kk*128 + tx*8];
            float4 b1 = *(const float4*)&KVs[kk*128 + tx*8 + 4];
            float bj[8] = {b0.x, b0.y, b0.z, b0.w, b1.x, b1.y, b1.z, b1.w};
#pragma unroll
            for (int j = 0; j < 8; j++) {
                o[0][j] = fmaf(a0, bj[j], o[0][j]);
                o[1][j] = fmaf(a1, bj[j], o[1][j]);
                o[2][j] = fmaf(a2, bj[j], o[2][j]);
                o[3][j] = fmaf(a3, bj[j], o[3][j]);
            }
        }
    }

    float* Ob = O + ((size_t)b * SEQ) * DIMV + (size_t)h * DHEAD;
#pragma unroll
    for (int i = 0; i < 4; i++) {
        const float inv = 1.f / l[i];
        float* dst = Ob + (size_t)(q0 + ty*4 + i) * DIMV + tx*8;
        *(float4*)dst       = make_float4(o[i][0]*inv, o[i][1]*inv, o[i][2]*inv, o[i][3]*inv);
        *(float4*)(dst + 4) = make_float4(o[i][4]*inv, o[i][5]*inv, o[i][6]*inv, o[i][7]*inv);
    }
}

// ---------------------------------------------------------------------------
extern "C" void kernel_launch(void* const* d_in, const int* in_sizes, int n_in,
                              void* d_out, int out_size)
{
    const float* hs  = (const float*)d_in[0];
    const float* rot = (const float*)d_in[1];
    const float* Wq  = (const float*)d_in[2];
    const float* bq  = (const float*)d_in[3];
    const float* Wk  = (const float*)d_in[4];
    const float* bk  = (const float*)d_in[5];
    const float* Wv  = (const float*)d_in[6];
    const float* bv  = (const float*)d_in[7];
    const float* nqw = (const float*)d_in[8];
    const float* nkw = (const float*)d_in[9];
    const float* hks = (const float*)d_in[10];
    const float* Wo  = (const float*)d_in[11];
    const float* bo  = (const float*)d_in[12];
    const int*   ocl = (const int*)d_in[13];
    float* out = (float*)d_out;

    float *qp, *kp, *vp, *ap;
    cudaGetSymbolAddress((void**)&qp, g_q);
    cudaGetSymbolAddress((void**)&kp, g_k);
    cudaGetSymbolAddress((void**)&vp, g_v);
    cudaGetSymbolAddress((void**)&ap, g_attn);

    __nv_bfloat16 *ahi, *alo, *wqh, *wql, *wkh, *wkl, *wvh, *wvl, *woh, *wol;
    cudaGetSymbolAddress((void**)&ahi, g_ahi);
    cudaGetSymbolAddress((void**)&alo, g_alo);
    cudaGetSymbolAddress((void**)&wqh, g_wqhi);
    cudaGetSymbolAddress((void**)&wql, g_wqlo);
    cudaGetSymbolAddress((void**)&wkh, g_wkhi);
    cudaGetSymbolAddress((void**)&wkl, g_wklo);
    cudaGetSymbolAddress((void**)&wvh, g_wvhi);
    cudaGetSymbolAddress((void**)&wvl, g_wvlo);
    cudaGetSymbolAddress((void**)&woh, g_wohi);
    cudaGetSymbolAddress((void**)&wol, g_wolo);

    const int nAct = MROWS * DIMV;       // 8.4M
    const int nW   = DIMV * DIMV;        // 4.2M

    split_kernel<<<nAct / 1024, 256>>>(hs, ahi, alo, nAct);
    split_kernel<<<nW / 1024, 256>>>(Wq, wqh, wql, nW);
    split_kernel<<<nW / 1024, 256>>>(Wk, wkh, wkl, nW);
    split_kernel<<<nW / 1024, 256>>>(Wv, wvh, wvl, nW);
    split_kernel<<<nW / 1024, 256>>>(Wo, woh, wol, nW);

    cudaFuncSetAttribute(gemm_mma_kernel,
                         cudaFuncAttributeMaxDynamicSharedMemorySize, GEMM_SMEM);
    dim3 gg(DIMV / 128, MROWS / 128);   // (16, 32)
    gemm_mma_kernel<<<gg, 256, GEMM_SMEM>>>(ahi, alo, wqh, wql, bq, qp);
    gemm_mma_kernel<<<gg, 256, GEMM_SMEM>>>(ahi, alo, wkh, wkl, bk, kp);
    gemm_mma_kernel<<<gg, 256, GEMM_SMEM>>>(ahi, alo, wvh, wvl, bv, vp);

    normrope_kernel<<<MROWS, 256>>>(qp, kp, rot, nqw, nkw, hks, ocl);

    cudaFuncSetAttribute(flashattn_kernel,
                         cudaFuncAttributeMaxDynamicSharedMemorySize, (int)ATT_SMEM);
    flashattn_kernel<<<dim3(SEQ / BQ, BATCH * HEADS), 256, ATT_SMEM>>>(qp, kp, vp, ap);

    split_kernel<<<nAct / 1024, 256>>>(ap, ahi, alo, nAct);
    gemm_mma_kernel<<<gg, 256, GEMM_SMEM>>>(ahi, alo, woh, wol, bo, out);
}

// round 6
// speedup vs baseline: 1.7803x; 1.7803x over previous
#include <cuda_runtime.h>
#include <cuda_bf16.h>
#include <math.h>
#include <cstdint>

#define DIMV    2048
#define SEQ     2048
#define BATCH   2
#define HEADS   16
#define DHEAD   128
#define MROWS   (BATCH*SEQ)   // 4096
#define EPSV    1e-5f

// ---------------- scratch (device globals; no allocation allowed) ----------
__device__ float g_q[(size_t)MROWS * DIMV];
__device__ float g_k[(size_t)MROWS * DIMV];
__device__ float g_v[(size_t)MROWS * DIMV];
__device__ float g_attn[(size_t)MROWS * DIMV];
__device__ __nv_bfloat16 g_ahi[(size_t)MROWS * DIMV];
__device__ __nv_bfloat16 g_alo[(size_t)MROWS * DIMV];
__device__ __nv_bfloat16 g_wqhi[(size_t)DIMV * DIMV];
__device__ __nv_bfloat16 g_wqlo[(size_t)DIMV * DIMV];
__device__ __nv_bfloat16 g_wkhi[(size_t)DIMV * DIMV];
__device__ __nv_bfloat16 g_wklo[(size_t)DIMV * DIMV];
__device__ __nv_bfloat16 g_wvhi[(size_t)DIMV * DIMV];
__device__ __nv_bfloat16 g_wvlo[(size_t)DIMV * DIMV];
__device__ __nv_bfloat16 g_wohi[(size_t)DIMV * DIMV];
__device__ __nv_bfloat16 g_wolo[(size_t)DIMV * DIMV];

// ---------------- arch-neutral tensor helpers (compute_103-safe) -----------
__device__ __forceinline__ uint32_t smem_u32(const void* p) {
    uint32_t a;
    asm("{ .reg .u64 t; cvta.to.shared.u64 t, %1; cvt.u32.u64 %0, t; }"
        : "=r"(a) : "l"(p));
    return a;
}
__device__ __forceinline__ void ldsm4(uint32_t* r, uint32_t addr) {
    asm volatile("ldmatrix.sync.aligned.m8n8.x4.shared.b16 {%0,%1,%2,%3}, [%4];"
                 : "=r"(r[0]), "=r"(r[1]), "=r"(r[2]), "=r"(r[3]) : "r"(addr));
}
__device__ __forceinline__ void mma16816(float* c, const uint32_t* a, const uint32_t* b) {
    asm volatile("mma.sync.aligned.m16n8k16.row.col.f32.bf16.bf16.f32 "
                 "{%0,%1,%2,%3}, {%4,%5,%6,%7}, {%8,%9}, {%0,%1,%2,%3};"
                 : "+f"(c[0]), "+f"(c[1]), "+f"(c[2]), "+f"(c[3])
                 : "r"(a[0]), "r"(a[1]), "r"(a[2]), "r"(a[3]), "r"(b[0]), "r"(b[1]));
}
#define CP_ASYNC16(dst, src) asm volatile("cp.async.cg.shared.global [%0], [%1], 16;" :: "r"(dst), "l"(src))
#define CP_COMMIT()          asm volatile("cp.async.commit_group;" ::: "memory")
#define CP_WAIT1()           asm volatile("cp.async.wait_group 1;" ::: "memory")
#define CP_WAIT0()           asm volatile("cp.async.wait_group 0;" ::: "memory")

// ---------------------------------------------------------------------------
// fp32 -> bf16 hi/lo split (vectorized x4)
// ---------------------------------------------------------------------------
__global__ __launch_bounds__(256)
void split_kernel(const float* __restrict__ x, __nv_bfloat16* __restrict__ hi,
                  __nv_bfloat16* __restrict__ lo, int n)
{
    int i = (blockIdx.x * blockDim.x + threadIdx.x) * 4;
    if (i >= n) return;
    float4 v = *(const float4*)(x + i);
    __nv_bfloat16 h0 = __float2bfloat16(v.x);
    __nv_bfloat16 h1 = __float2bfloat16(v.y);
    __nv_bfloat16 h2 = __float2bfloat16(v.z);
    __nv_bfloat16 h3 = __float2bfloat16(v.w);
    __nv_bfloat16 l0 = __float2bfloat16(v.x - __bfloat162float(h0));
    __nv_bfloat16 l1 = __float2bfloat16(v.y - __bfloat162float(h1));
    __nv_bfloat16 l2 = __float2bfloat16(v.z - __bfloat162float(h2));
    __nv_bfloat16 l3 = __float2bfloat16(v.w - __bfloat162float(h3));
    *(__nv_bfloat162*)(hi + i)     = __nv_bfloat162(h0, h1);
    *(__nv_bfloat162*)(hi + i + 2) = __nv_bfloat162(h2, h3);
    *(__nv_bfloat162*)(lo + i)     = __nv_bfloat162(l0, l1);
    *(__nv_bfloat162*)(lo + i + 2) = __nv_bfloat162(l2, l3);
}

// ---------------------------------------------------------------------------
// bf16 3-term mma.sync GEMM: C[4096,2048] = (Ahi+Alo) @ (Bhi+Blo)^T + bias
// CTA tile 128(M)x256(N), BK=64, SW128 swizzled smem (conflict-free cp.async
// stores AND ldmatrix reads), double-buffered. 8 warps (2x4), warp 64x64.
// ---------------------------------------------------------------------------
#define BUF_STRIDE 98304               // Ahi 16K + Alo 16K + Bhi 32K + Blo 32K
#define GEMM_SMEM  (2 * BUF_STRIDE)    // 192 KB

__global__ __launch_bounds__(256, 1)
void gemm_mma_kernel(const __nv_bfloat16* __restrict__ Ahi, const __nv_bfloat16* __restrict__ Alo,
                     const __nv_bfloat16* __restrict__ Bhi, const __nv_bfloat16* __restrict__ Blo,
                     const float* __restrict__ bias, float* __restrict__ C)
{
    extern __shared__ __align__(1024) char smem[];
    const uint32_t sb = smem_u32(smem);

    const int tid  = threadIdx.x;
    const int wid  = tid >> 5;
    const int lane = tid & 31;
    const int wm   = wid >> 2;          // 0..1  (64 M-rows each)
    const int wn   = wid & 3;           // 0..3  (64 N-cols each)
    const int m0   = blockIdx.y * 128;
    const int n0   = blockIdx.x * 256;

    // ---- stage loader: 6144 x 16B cp.async, SW128 chunk swizzle ----
    auto load_stage = [&](int k0, int buf) {
        const uint32_t bo = sb + buf * BUF_STRIDE;
        // A hi/lo: 2048 chunks (128 rows x 8 chunks x 2 planes)
#pragma unroll
        for (int j = 0; j < 8; j++) {
            const int c  = tid + j * 256;
            const int p  = c >> 10;            // 0=hi, 1=lo
            const int r  = (c >> 3) & 127;
            const int ch = c & 7;
            const uint32_t dst = bo + p * 16384 + (r << 7) + ((ch ^ (r & 7)) << 4);
            const __nv_bfloat16* src = (p ? Alo : Ahi)
                + (size_t)(m0 + r) * DIMV + k0 + ch * 8;
            CP_ASYNC16(dst, src);
        }
        // B hi/lo: 4096 chunks (256 rows x 8 chunks x 2 planes)
#pragma unroll
        for (int j = 0; j < 16; j++) {
            const int c  = tid + j * 256;
            const int p  = c >> 11;
            const int r  = (c >> 3) & 255;
            const int ch = c & 7;
            const uint32_t dst = bo + 32768 + p * 32768 + (r << 7) + ((ch ^ (r & 7)) << 4);
            const __nv_bfloat16* src = (p ? Blo : Bhi)
                + (size_t)(n0 + r) * DIMV + k0 + ch * 8;
            CP_ASYNC16(dst, src);
        }
    };

    float acc[4][8][4];
#pragma unroll
    for (int i = 0; i < 4; i++)
#pragma unroll
        for (int j = 0; j < 8; j++)
#pragma unroll
            for (int t = 0; t < 4; t++) acc[i][j][t] = 0.f;

    // ldmatrix lane components (same frag mapping that verified in R4)
    const int a_row = wm * 64 + (lane & 15);
    const int a_chx = lane >> 4;                       // +0/+1 chunk (k 0/8)
    const int b_row = wn * 64 + ((lane >> 4) << 3) + (lane & 7);
    const int b_chx = (lane >> 3) & 1;

    load_stage(0, 0);
    CP_COMMIT();

    for (int s = 0; s < 32; s++) {
        const int buf = s & 1;
        if (s + 1 < 32) { load_stage((s + 1) * 64, buf ^ 1); CP_COMMIT(); CP_WAIT1(); }
        else            { CP_WAIT0(); }
        __syncthreads();

        const uint32_t aH = sb + buf * BUF_STRIDE;
        const uint32_t aL = aH + 16384;
        const uint32_t bH = aH + 32768;
        const uint32_t bL = bH + 32768;

#pragma unroll
        for (int kk8 = 0; kk8 < 4; kk8++) {            // k16 steps within BK=64
            uint32_t ah[4][4], al[4][4], bh[8][2], bl[8][2];
            const int ach = kk8 * 2 + a_chx;
#pragma unroll
            for (int i = 0; i < 4; i++) {
                const int r = a_row + i * 16;
                const uint32_t ad = (r << 7) + ((ach ^ (r & 7)) << 4);
                ldsm4(ah[i], aH + ad);
                ldsm4(al[i], aL + ad);
            }
            const int bch = kk8 * 2 + b_chx;
#pragma unroll
            for (int jj = 0; jj < 4; jj++) {
                const int r = b_row + jj * 16;
                const uint32_t bd = (r << 7) + ((bch ^ (r & 7)) << 4);
                uint32_t t[4];
                ldsm4(t, bH + bd);
                bh[2*jj][0] = t[0];   bh[2*jj][1] = t[1];
                bh[2*jj+1][0] = t[2]; bh[2*jj+1][1] = t[3];
                ldsm4(t, bL + bd);
                bl[2*jj][0] = t[0];   bl[2*jj][1] = t[1];
                bl[2*jj+1][0] = t[2]; bl[2*jj+1][1] = t[3];
            }
#pragma unroll
            for (int i = 0; i < 4; i++)
#pragma unroll
                for (int j = 0; j < 8; j++) {
                    mma16816(acc[i][j], ah[i], bh[j]);
                    mma16816(acc[i][j], ah[i], bl[j]);
                    mma16816(acc[i][j], al[i], bh[j]);
                }
        }
        __syncthreads();
    }

    // ---- epilogue: bias + store ----
    const int mw = m0 + wm * 64;
    const int nw = n0 + wn * 64;
    const int ml = lane >> 2;
    const int nl = (lane & 3) * 2;
#pragma unroll
    for (int j = 0; j < 8; j++) {
        const int n = nw + j * 8 + nl;
        const float b0 = bias[n], b1 = bias[n + 1];
#pragma unroll
        for (int i = 0; i < 4; i++) {
            const int m = mw + i * 16 + ml;
            *(float2*)&C[(size_t)m * DIMV + n] =
                make_float2(acc[i][j][0] + b0, acc[i][j][1] + b1);
            *(float2*)&C[(size_t)(m + 8) * DIMV + n] =
                make_float2(acc[i][j][2] + b0, acc[i][j][3] + b1);
        }
    }
}

// ---------------------------------------------------------------------------
// Fused RMSNorm + interleaved RoPE + history-key scaling (unchanged)
// ---------------------------------------------------------------------------
__global__ __launch_bounds__(256)
void normrope_kernel(float* __restrict__ q, float* __restrict__ k,
                     const float* __restrict__ rot,
                     const float* __restrict__ wq, const float* __restrict__ wk,
                     const float* __restrict__ hks, const int* __restrict__ oclp)
{
    const int r   = blockIdx.x;
    const int s   = r & (SEQ - 1);
    const int tid = threadIdx.x;
    float* qrow = q + (size_t)r * DIMV;
    float* krow = k + (size_t)r * DIMV;
    const int base = tid * 8;

    float qa[8], ka[8];
    {
        float4 t0 = *(const float4*)(qrow + base);
        float4 t1 = *(const float4*)(qrow + base + 4);
        qa[0]=t0.x; qa[1]=t0.y; qa[2]=t0.z; qa[3]=t0.w;
        qa[4]=t1.x; qa[5]=t1.y; qa[6]=t1.z; qa[7]=t1.w;
        float4 u0 = *(const float4*)(krow + base);
        float4 u1 = *(const float4*)(krow + base + 4);
        ka[0]=u0.x; ka[1]=u0.y; ka[2]=u0.z; ka[3]=u0.w;
        ka[4]=u1.x; ka[5]=u1.y; ka[6]=u1.z; ka[7]=u1.w;
    }

    float sq = 0.f, sk = 0.f;
#pragma unroll
    for (int i = 0; i < 8; i++) { sq = fmaf(qa[i], qa[i], sq); sk = fmaf(ka[i], ka[i], sk); }

    __shared__ float2 red[256];
    red[tid] = make_float2(sq, sk);
    __syncthreads();
#pragma unroll
    for (int off = 128; off > 0; off >>= 1) {
        if (tid < off) {
            red[tid].x += red[tid + off].x;
            red[tid].y += red[tid + off].y;
        }
        __syncthreads();
    }
    const float rq = rsqrtf(red[0].x * (1.f / DIMV) + EPSV);
    const float rk = rsqrtf(red[0].y * (1.f / DIMV) + EPSV);

    const int  hist    = SEQ - oclp[0];
    const bool is_hist = (s < hist);
    const float* rrow  = rot + (size_t)s * (2 * DHEAD);

    float qo[8], ko[8];
#pragma unroll
    for (int t = 0; t < 4; t++) {
        const int p = (base >> 1) + t;
        const int h = p >> 6;
        const int i = p & 63;
        const float c  = rrow[2*i];
        const float si = rrow[DHEAD + 2*i + 1];
        const int n = base + 2*t;
        float q1 = qa[2*t]     * rq * wq[n];
        float q2 = qa[2*t + 1] * rq * wq[n + 1];
        qo[2*t]     = q1*c - q2*si;
        qo[2*t + 1] = q1*si + q2*c;
        float k1 = ka[2*t]     * rk * wk[n];
        float k2 = ka[2*t + 1] * rk * wk[n + 1];
        float ke  = k1*c - k2*si;
        float kod = k1*si + k2*c;
        if (is_hist) {
            const float sc = 1.f + 9.f / (1.f + __expf(-hks[h]));
            ke *= sc; kod *= sc;
        }
        ko[2*t] = ke; ko[2*t + 1] = kod;
    }
    *(float4*)(qrow + base)     = make_float4(qo[0], qo[1], qo[2], qo[3]);
    *(float4*)(qrow + base + 4) = make_float4(qo[4], qo[5], qo[6], qo[7]);
    *(float4*)(krow + base)     = make_float4(ko[0], ko[1], ko[2], ko[3]);
    *(float4*)(krow + base + 4) = make_float4(ko[4], ko[5], ko[6], ko[7]);
}

// ---------------------------------------------------------------------------
// Flash attention fp32 (unchanged — at the FFMA roofline; f32x2 next round)
// ---------------------------------------------------------------------------
#define BQ  64
#define BKV 64
#define ATT_SMEM ((128*64*2 + 64*64) * sizeof(float))

__global__ __launch_bounds__(256, 2)
void flashattn_kernel(const float* __restrict__ Q, const float* __restrict__ K,
                      const float* __restrict__ V, float* __restrict__ O)
{
    extern __shared__ float smf[];
    float* Qs  = smf;
    float* KVs = smf + 128*64;
    float* Ps  = smf + 2*128*64;

    const int tid = threadIdx.x;
    const int tx  = tid & 15;
    const int ty  = tid >> 4;
    const int bh  = blockIdx.y;
    const int b   = bh >> 4;
    const int h   = bh & 15;
    const int q0  = blockIdx.x * BQ;

    const float* Qb = Q + ((size_t)b * SEQ) * DIMV + (size_t)h * DHEAD;
    const float* Kb = K + ((size_t)b * SEQ) * DIMV + (size_t)h * DHEAD;
    const float* Vb = V + ((size_t)b * SEQ) * DIMV + (size_t)h * DHEAD;

    const int lrow  = tid >> 2;
    const int dpart = (tid & 3) * 32;

    {
        const float* src = Qb + (size_t)(q0 + lrow) * DIMV + dpart;
#pragma unroll
        for (int j = 0; j < 8; j++) {
            float4 v4 = *(const float4*)(src + j*4);
            const int d = dpart + j*4;
            Qs[(d+0)*64 + lrow] = v4.x; Qs[(d+1)*64 + lrow] = v4.y;
            Qs[(d+2)*64 + lrow] = v4.z; Qs[(d+3)*64 + lrow] = v4.w;
        }
    }

    float o[4][8];
#pragma unroll
    for (int i = 0; i < 4; i++)
#pragma unroll
        for (int j = 0; j < 8; j++) o[i][j] = 0.f;
    float mprev[4] = {-INFINITY, -INFINITY, -INFINITY, -INFINITY};
    float l[4]     = {0.f, 0.f, 0.f, 0.f};
    const float SCALE = 0.08838834764831845f;

    for (int kv0 = 0; kv0 < SEQ; kv0 += BKV) {
        __syncthreads();
        {
            const float* src = Kb + (size_t)(kv0 + lrow) * DIMV + dpart;
#pragma unroll
            for (int j = 0; j < 8; j++) {
                float4 v4 = *(const float4*)(src + j*4);
                const int d = dpart + j*4;
                KVs[(d+0)*64 + lrow] = v4.x; KVs[(d+1)*64 + lrow] = v4.y;
                KVs[(d+2)*64 + lrow] = v4.z; KVs[(d+3)*64 + lrow] = v4.w;
            }
        }
        __syncthreads();

        float sacc[4][4];
#pragma unroll
        for (int i = 0; i < 4; i++)
#pragma unroll
            for (int j = 0; j < 4; j++) sacc[i][j] = 0.f;
#pragma unroll 8
        for (int d = 0; d < 128; d++) {
            float4 aq = *(const float4*)&Qs[d*64 + ty*4];
            float4 bk = *(const float4*)&KVs[d*64 + tx*4];
            float a[4] = {aq.x, aq.y, aq.z, aq.w};
            float bb[4] = {bk.x, bk.y, bk.z, bk.w};
#pragma unroll
            for (int i = 0; i < 4; i++)
#pragma unroll
                for (int j = 0; j < 4; j++)
                    sacc[i][j] = fmaf(a[i], bb[j], sacc[i][j]);
        }

#pragma unroll
        for (int i = 0; i < 4; i++) {
            float rmax = -INFINITY;
#pragma unroll
            for (int j = 0; j < 4; j++) { sacc[i][j] *= SCALE; rmax = fmaxf(rmax, sacc[i][j]); }
            rmax = fmaxf(rmax, __shfl_xor_sync(0xffffffffu, rmax, 8));
            rmax = fmaxf(rmax, __shfl_xor_sync(0xffffffffu, rmax, 4));
            rmax = fmaxf(rmax, __shfl_xor_sync(0xffffffffu, rmax, 2));
            rmax = fmaxf(rmax, __shfl_xor_sync(0xffffffffu, rmax, 1));
            const float mnew = fmaxf(mprev[i], rmax);
            float p0 = __expf(sacc[i][0] - mnew);
            float p1 = __expf(sacc[i][1] - mnew);
            float p2 = __expf(sacc[i][2] - mnew);
            float p3 = __expf(sacc[i][3] - mnew);
            float rsum = p0 + p1 + p2 + p3;
            rsum += __shfl_xor_sync(0xffffffffu, rsum, 8);
            rsum += __shfl_xor_sync(0xffffffffu, rsum, 4);
            rsum += __shfl_xor_sync(0xffffffffu, rsum, 2);
            rsum += __shfl_xor_sync(0xffffffffu, rsum, 1);
            const float alpha = __expf(mprev[i] - mnew);
            l[i] = l[i] * alpha + rsum;
            mprev[i] = mnew;
            *(float4*)&Ps[(ty*4 + i)*64 + tx*4] = make_float4(p0, p1, p2, p3);
#pragma unroll
            for (int j = 0; j < 8; j++) o[i][j] *= alpha;
        }
        __syncthreads();

        {
            const float* src = Vb + (size_t)(kv0 + lrow) * DIMV + dpart;
#pragma unroll
            for (int j = 0; j < 8; j++)
                *(float4*)&KVs[lrow*128 + dpart + j*4] = *(const float4*)(src + j*4);
        }
        __syncthreads();

#pragma unroll 4
        for (int kk = 0; kk < BKV; kk++) {
            float a0 = Ps[(ty*4 + 0)*64 + kk];
            float a1 = Ps[(ty*4 + 1)*64 + kk];
            float a2 = Ps[(ty*4 + 2)*64 + kk];
            float a3 = Ps[(ty*4 + 3)*64 + kk];
            float4 b0 = *(const float4*)&KVs[kk*128 + tx*8];
            float4 b1 = *(const float4*)&KVs[kk*128 + tx*8 + 4];
            float bj[8] = {b0.x, b0.y, b0.z, b0.w, b1.x, b1.y, b1.z, b1.w};
#pragma unroll
            for (int j = 0; j < 8; j++) {
                o[0][j] = fmaf(a0, bj[j], o[0][j]);
                o[1][j] = fmaf(a1, bj[j], o[1][j]);
                o[2][j] = fmaf(a2, bj[j], o[2][j]);
                o[3][j] = fmaf(a3, bj[j], o[3][j]);
            }
        }
    }

    float* Ob = O + ((size_t)b * SEQ) * DIMV + (size_t)h * DHEAD;
#pragma unroll
    for (int i = 0; i < 4; i++) {
        const float inv = 1.f / l[i];
        float* dst = Ob + (size_t)(q0 + ty*4 + i) * DIMV + tx*8;
        *(float4*)dst       = make_float4(o[i][0]*inv, o[i][1]*inv, o[i][2]*inv, o[i][3]*inv);
        *(float4*)(dst + 4) = make_float4(o[i][4]*inv, o[i][5]*inv, o[i][6]*inv, o[i][7]*inv);
    }
}

// ---------------------------------------------------------------------------
extern "C" void kernel_launch(void* const* d_in, const int* in_sizes, int n_in,
                              void* d_out, int out_size)
{
    const float* hs  = (const float*)d_in[0];
    const float* rot = (const float*)d_in[1];
    const float* Wq  = (const float*)d_in[2];
    const float* bq  = (const float*)d_in[3];
    const float* Wk  = (const float*)d_in[4];
    const float* bk  = (const float*)d_in[5];
    const float* Wv  = (const float*)d_in[6];
    const float* bv  = (const float*)d_in[7];
    const float* nqw = (const float*)d_in[8];
    const float* nkw = (const float*)d_in[9];
    const float* hks = (const float*)d_in[10];
    const float* Wo  = (const float*)d_in[11];
    const float* bo  = (const float*)d_in[12];
    const int*   ocl = (const int*)d_in[13];
    float* out = (float*)d_out;

    float *qp, *kp, *vp, *ap;
    cudaGetSymbolAddress((void**)&qp, g_q);
    cudaGetSymbolAddress((void**)&kp, g_k);
    cudaGetSymbolAddress((void**)&vp, g_v);
    cudaGetSymbolAddress((void**)&ap, g_attn);

    __nv_bfloat16 *ahi, *alo, *wqh, *wql, *wkh, *wkl, *wvh, *wvl, *woh, *wol;
    cudaGetSymbolAddress((void**)&ahi, g_ahi);
    cudaGetSymbolAddress((void**)&alo, g_alo);
    cudaGetSymbolAddress((void**)&wqh, g_wqhi);
    cudaGetSymbolAddress((void**)&wql, g_wqlo);
    cudaGetSymbolAddress((void**)&wkh, g_wkhi);
    cudaGetSymbolAddress((void**)&wkl, g_wklo);
    cudaGetSymbolAddress((void**)&wvh, g_wvhi);
    cudaGetSymbolAddress((void**)&wvl, g_wvlo);
    cudaGetSymbolAddress((void**)&woh, g_wohi);
    cudaGetSymbolAddress((void**)&wol, g_wolo);

    const int nAct = MROWS * DIMV;       // 8.4M
    const int nW   = DIMV * DIMV;        // 4.2M

    split_kernel<<<nAct / 1024, 256>>>(hs, ahi, alo, nAct);
    split_kernel<<<nW / 1024, 256>>>(Wq, wqh, wql, nW);
    split_kernel<<<nW / 1024, 256>>>(Wk, wkh, wkl, nW);
    split_kernel<<<nW / 1024, 256>>>(Wv, wvh, wvl, nW);
    split_kernel<<<nW / 1024, 256>>>(Wo, woh, wol, nW);

    cudaFuncSetAttribute(gemm_mma_kernel,
                         cudaFuncAttributeMaxDynamicSharedMemorySize, GEMM_SMEM);
    dim3 gg(DIMV / 256, MROWS / 128);   // (8, 32)
    gemm_mma_kernel<<<gg, 256, GEMM_SMEM>>>(ahi, alo, wqh, wql, bq, qp);
    gemm_mma_kernel<<<gg, 256, GEMM_SMEM>>>(ahi, alo, wkh, wkl, bk, kp);
    gemm_mma_kernel<<<gg, 256, GEMM_SMEM>>>(ahi, alo, wvh, wvl, bv, vp);

    normrope_kernel<<<MROWS, 256>>>(qp, kp, rot, nqw, nkw, hks, ocl);

    cudaFuncSetAttribute(flashattn_kernel,
                         cudaFuncAttributeMaxDynamicSharedMemorySize, (int)ATT_SMEM);
    flashattn_kernel<<<dim3(SEQ / BQ, BATCH * HEADS), 256, ATT_SMEM>>>(qp, kp, vp, ap);

    split_kernel<<<nAct / 1024, 256>>>(ap, ahi, alo, nAct);
    gemm_mma_kernel<<<gg, 256, GEMM_SMEM>>>(ahi, alo, woh, wol, bo, out);
}

// round 9
// speedup vs baseline: 4.0340x; 2.2659x over previous
#include <cuda_runtime.h>
#include <cuda_bf16.h>
#include <math.h>
#include <cstdint>

#define DIMV    2048
#define SEQ     2048
#define BATCH   2
#define HEADS   16
#define DHEAD   128
#define MROWS   (BATCH*SEQ)   // 4096
#define EPSV    1e-5f

// ---------------- scratch (device globals; no allocation allowed) ----------
__device__ float g_q[(size_t)MROWS * DIMV];
__device__ float g_k[(size_t)MROWS * DIMV];
__device__ float g_v[(size_t)MROWS * DIMV];
__device__ float g_attn[(size_t)MROWS * DIMV];
__device__ __nv_bfloat16 g_ahi[(size_t)MROWS * DIMV];
__device__ __nv_bfloat16 g_alo[(size_t)MROWS * DIMV];
__device__ __nv_bfloat16 g_khi[(size_t)MROWS * DIMV];
__device__ __nv_bfloat16 g_klo[(size_t)MROWS * DIMV];
__device__ __nv_bfloat16 g_vhi[(size_t)MROWS * DIMV];
__device__ __nv_bfloat16 g_vlo[(size_t)MROWS * DIMV];
__device__ __nv_bfloat16 g_wqhi[(size_t)DIMV * DIMV];
__device__ __nv_bfloat16 g_wqlo[(size_t)DIMV * DIMV];
__device__ __nv_bfloat16 g_wkhi[(size_t)DIMV * DIMV];
__device__ __nv_bfloat16 g_wklo[(size_t)DIMV * DIMV];
__device__ __nv_bfloat16 g_wvhi[(size_t)DIMV * DIMV];
__device__ __nv_bfloat16 g_wvlo[(size_t)DIMV * DIMV];
__device__ __nv_bfloat16 g_wohi[(size_t)DIMV * DIMV];
__device__ __nv_bfloat16 g_wolo[(size_t)DIMV * DIMV];

// ---------------- arch-neutral tensor helpers (compute_103-safe) -----------
__device__ __forceinline__ uint32_t smem_u32(const void* p) {
    uint32_t a;
    asm("{ .reg .u64 t; cvta.to.shared.u64 t, %1; cvt.u32.u64 %0, t; }"
        : "=r"(a) : "l"(p));
    return a;
}
__device__ __forceinline__ void ldsm4(uint32_t* r, uint32_t addr) {
    asm volatile("ldmatrix.sync.aligned.m8n8.x4.shared.b16 {%0,%1,%2,%3}, [%4];"
                 : "=r"(r[0]), "=r"(r[1]), "=r"(r[2]), "=r"(r[3]) : "r"(addr));
}
__device__ __forceinline__ void ldsm4t(uint32_t* r, uint32_t addr) {
    asm volatile("ldmatrix.sync.aligned.m8n8.x4.trans.shared.b16 {%0,%1,%2,%3}, [%4];"
                 : "=r"(r[0]), "=r"(r[1]), "=r"(r[2]), "=r"(r[3]) : "r"(addr));
}
__device__ __forceinline__ void mma16816(float* c, const uint32_t* a, const uint32_t* b) {
    asm volatile("mma.sync.aligned.m16n8k16.row.col.f32.bf16.bf16.f32 "
                 "{%0,%1,%2,%3}, {%4,%5,%6,%7}, {%8,%9}, {%0,%1,%2,%3};"
                 : "+f"(c[0]), "+f"(c[1]), "+f"(c[2]), "+f"(c[3])
                 : "r"(a[0]), "r"(a[1]), "r"(a[2]), "r"(a[3]), "r"(b[0]), "r"(b[1]));
}
// pack two fp32 into bf16x2 hi + residual-lo bf16x2
__device__ __forceinline__ void psplit(float f0, float f1, uint32_t& h, uint32_t& l) {
    asm("cvt.rn.bf16x2.f32 %0, %1, %2;" : "=r"(h) : "f"(f1), "f"(f0));
    const float h0 = __uint_as_float(h << 16);
    const float h1 = __uint_as_float(h & 0xffff0000u);
    const float l0 = f0 - h0, l1 = f1 - h1;
    asm("cvt.rn.bf16x2.f32 %0, %1, %2;" : "=r"(l) : "f"(l1), "f"(l0));
}
#define CP_ASYNC16(dst, src) asm volatile("cp.async.cg.shared.global [%0], [%1], 16;" :: "r"(dst), "l"(src))
#define CP_COMMIT()          asm volatile("cp.async.commit_group;" ::: "memory")
#define CP_WAIT1()           asm volatile("cp.async.wait_group 1;" ::: "memory")
#define CP_WAIT0()           asm volatile("cp.async.wait_group 0;" ::: "memory")
// swizzled offset within a 256B-row tile (16B chunks)
__device__ __forceinline__ uint32_t SWZ(int r, int ch) {
    return (uint32_t)((r << 8) + (((ch & 7) ^ (r & 7)) << 4) + ((ch & 8) << 4));
}

// ---------------------------------------------------------------------------
// fp32 -> bf16 hi/lo split (vectorized x4)
// ---------------------------------------------------------------------------
__global__ __launch_bounds__(256)
void split_kernel(const float* __restrict__ x, __nv_bfloat16* __restrict__ hi,
                  __nv_bfloat16* __restrict__ lo, int n)
{
    int i = (blockIdx.x * blockDim.x + threadIdx.x) * 4;
    if (i >= n) return;
    float4 v = *(const float4*)(x + i);
    __nv_bfloat16 h0 = __float2bfloat16(v.x);
    __nv_bfloat16 h1 = __float2bfloat16(v.y);
    __nv_bfloat16 h2 = __float2bfloat16(v.z);
    __nv_bfloat16 h3 = __float2bfloat16(v.w);
    __nv_bfloat16 l0 = __float2bfloat16(v.x - __bfloat162float(h0));
    __nv_bfloat16 l1 = __float2bfloat16(v.y - __bfloat162float(h1));
    __nv_bfloat16 l2 = __float2bfloat16(v.z - __bfloat162float(h2));
    __nv_bfloat16 l3 = __float2bfloat16(v.w - __bfloat162float(h3));
    *(__nv_bfloat162*)(hi + i)     = __nv_bfloat162(h0, h1);
    *(__nv_bfloat162*)(hi + i + 2) = __nv_bfloat162(h2, h3);
    *(__nv_bfloat162*)(lo + i)     = __nv_bfloat162(l0, l1);
    *(__nv_bfloat162*)(lo + i + 2) = __nv_bfloat162(l2, l3);
}

// ---------------------------------------------------------------------------
// bf16 3-term mma.sync GEMM (unchanged from R6 — verified)
// ---------------------------------------------------------------------------
#define BUF_STRIDE 98304
#define GEMM_SMEM  (2 * BUF_STRIDE)

__global__ __launch_bounds__(256, 1)
void gemm_mma_kernel(const __nv_bfloat16* __restrict__ Ahi, const __nv_bfloat16* __restrict__ Alo,
                     const __nv_bfloat16* __restrict__ Bhi, const __nv_bfloat16* __restrict__ Blo,
                     const float* __restrict__ bias, float* __restrict__ C)
{
    extern __shared__ __align__(1024) char smem[];
    const uint32_t sb = smem_u32(smem);

    const int tid  = threadIdx.x;
    const int wid  = tid >> 5;
    const int lane = tid & 31;
    const int wm   = wid >> 2;
    const int wn   = wid & 3;
    const int m0   = blockIdx.y * 128;
    const int n0   = blockIdx.x * 256;

    auto load_stage = [&](int k0, int buf) {
        const uint32_t bo = sb + buf * BUF_STRIDE;
#pragma unroll
        for (int j = 0; j < 8; j++) {
            const int c  = tid + j * 256;
            const int p  = c >> 10;
            const int r  = (c >> 3) & 127;
            const int ch = c & 7;
            const uint32_t dst = bo + p * 16384 + (r << 7) + ((ch ^ (r & 7)) << 4);
            const __nv_bfloat16* src = (p ? Alo : Ahi)
                + (size_t)(m0 + r) * DIMV + k0 + ch * 8;
            CP_ASYNC16(dst, src);
        }
#pragma unroll
        for (int j = 0; j < 16; j++) {
            const int c  = tid + j * 256;
            const int p  = c >> 11;
            const int r  = (c >> 3) & 255;
            const int ch = c & 7;
            const uint32_t dst = bo + 32768 + p * 32768 + (r << 7) + ((ch ^ (r & 7)) << 4);
            const __nv_bfloat16* src = (p ? Blo : Bhi)
                + (size_t)(n0 + r) * DIMV + k0 + ch * 8;
            CP_ASYNC16(dst, src);
        }
    };

    float acc[4][8][4];
#pragma unroll
    for (int i = 0; i < 4; i++)
#pragma unroll
        for (int j = 0; j < 8; j++)
#pragma unroll
            for (int t = 0; t < 4; t++) acc[i][j][t] = 0.f;

    const int a_row = wm * 64 + (lane & 15);
    const int a_chx = lane >> 4;
    const int b_row = wn * 64 + ((lane >> 4) << 3) + (lane & 7);
    const int b_chx = (lane >> 3) & 1;

    load_stage(0, 0);
    CP_COMMIT();

    for (int s = 0; s < 32; s++) {
        const int buf = s & 1;
        if (s + 1 < 32) { load_stage((s + 1) * 64, buf ^ 1); CP_COMMIT(); CP_WAIT1(); }
        else            { CP_WAIT0(); }
        __syncthreads();

        const uint32_t aH = sb + buf * BUF_STRIDE;
        const uint32_t aL = aH + 16384;
        const uint32_t bH = aH + 32768;
        const uint32_t bL = bH + 32768;

#pragma unroll
        for (int kk8 = 0; kk8 < 4; kk8++) {
            uint32_t ah[4][4], al[4][4], bh[8][2], bl[8][2];
            const int ach = kk8 * 2 + a_chx;
#pragma unroll
            for (int i = 0; i < 4; i++) {
                const int r = a_row + i * 16;
                const uint32_t ad = (r << 7) + ((ach ^ (r & 7)) << 4);
                ldsm4(ah[i], aH + ad);
                ldsm4(al[i], aL + ad);
            }
            const int bch = kk8 * 2 + b_chx;
#pragma unroll
            for (int jj = 0; jj < 4; jj++) {
                const int r = b_row + jj * 16;
                const uint32_t bd = (r << 7) + ((bch ^ (r & 7)) << 4);
                uint32_t t[4];
                ldsm4(t, bH + bd);
                bh[2*jj][0] = t[0];   bh[2*jj][1] = t[1];
                bh[2*jj+1][0] = t[2]; bh[2*jj+1][1] = t[3];
                ldsm4(t, bL + bd);
                bl[2*jj][0] = t[0];   bl[2*jj][1] = t[1];
                bl[2*jj+1][0] = t[2]; bl[2*jj+1][1] = t[3];
            }
#pragma unroll
            for (int i = 0; i < 4; i++)
#pragma unroll
                for (int j = 0; j < 8; j++) {
                    mma16816(acc[i][j], ah[i], bh[j]);
                    mma16816(acc[i][j], ah[i], bl[j]);
                    mma16816(acc[i][j], al[i], bh[j]);
                }
        }
        __syncthreads();
    }

    const int mw = m0 + wm * 64;
    const int nw = n0 + wn * 64;
    const int ml = lane >> 2;
    const int nl = (lane & 3) * 2;
#pragma unroll
    for (int j = 0; j < 8; j++) {
        const int n = nw + j * 8 + nl;
        const float b0 = bias[n], b1 = bias[n + 1];
#pragma unroll
        for (int i = 0; i < 4; i++) {
            const int m = mw + i * 16 + ml;
            *(float2*)&C[(size_t)m * DIMV + n] =
                make_float2(acc[i][j][0] + b0, acc[i][j][1] + b1);
            *(float2*)&C[(size_t)(m + 8) * DIMV + n] =
                make_float2(acc[i][j][2] + b0, acc[i][j][3] + b1);
        }
    }
}

// ---------------------------------------------------------------------------
// Fused RMSNorm + interleaved RoPE + history-key scaling (unchanged)
// ---------------------------------------------------------------------------
__global__ __launch_bounds__(256)
void normrope_kernel(float* __restrict__ q, float* __restrict__ k,
                     const float* __restrict__ rot,
                     const float* __restrict__ wq, const float* __restrict__ wk,
                     const float* __restrict__ hks, const int* __restrict__ oclp)
{
    const int r   = blockIdx.x;
    const int s   = r & (SEQ - 1);
    const int tid = threadIdx.x;
    float* qrow = q + (size_t)r * DIMV;
    float* krow = k + (size_t)r * DIMV;
    const int base = tid * 8;

    float qa[8], ka[8];
    {
        float4 t0 = *(const float4*)(qrow + base);
        float4 t1 = *(const float4*)(qrow + base + 4);
        qa[0]=t0.x; qa[1]=t0.y; qa[2]=t0.z; qa[3]=t0.w;
        qa[4]=t1.x; qa[5]=t1.y; qa[6]=t1.z; qa[7]=t1.w;
        float4 u0 = *(const float4*)(krow + base);
        float4 u1 = *(const float4*)(krow + base + 4);
        ka[0]=u0.x; ka[1]=u0.y; ka[2]=u0.z; ka[3]=u0.w;
        ka[4]=u1.x; ka[5]=u1.y; ka[6]=u1.z; ka[7]=u1.w;
    }

    float sq = 0.f, sk = 0.f;
#pragma unroll
    for (int i = 0; i < 8; i++) { sq = fmaf(qa[i], qa[i], sq); sk = fmaf(ka[i], ka[i], sk); }

    __shared__ float2 red[256];
    red[tid] = make_float2(sq, sk);
    __syncthreads();
#pragma unroll
    for (int off = 128; off > 0; off >>= 1) {
        if (tid < off) {
            red[tid].x += red[tid + off].x;
            red[tid].y += red[tid + off].y;
        }
        __syncthreads();
    }
    const float rq = rsqrtf(red[0].x * (1.f / DIMV) + EPSV);
    const float rk = rsqrtf(red[0].y * (1.f / DIMV) + EPSV);

    const int  hist    = SEQ - oclp[0];
    const bool is_hist = (s < hist);
    const float* rrow  = rot + (size_t)s * (2 * DHEAD);

    float qo[8], ko[8];
#pragma unroll
    for (int t = 0; t < 4; t++) {
        const int p = (base >> 1) + t;
        const int h = p >> 6;
        const int i = p & 63;
        const float c  = rrow[2*i];
        const float si = rrow[DHEAD + 2*i + 1];
        const int n = base + 2*t;
        float q1 = qa[2*t]     * rq * wq[n];
        float q2 = qa[2*t + 1] * rq * wq[n + 1];
        qo[2*t]     = q1*c - q2*si;
        qo[2*t + 1] = q1*si + q2*c;
        float k1 = ka[2*t]     * rk * wk[n];
        float k2 = ka[2*t + 1] * rk * wk[n + 1];
        float ke  = k1*c - k2*si;
        float kod = k1*si + k2*c;
        if (is_hist) {
            const float sc = 1.f + 9.f / (1.f + __expf(-hks[h]));
            ke *= sc; kod *= sc;
        }
        ko[2*t] = ke; ko[2*t + 1] = kod;
    }
    *(float4*)(qrow + base)     = make_float4(qo[0], qo[1], qo[2], qo[3]);
    *(float4*)(qrow + base + 4) = make_float4(qo[4], qo[5], qo[6], qo[7]);
    *(float4*)(krow + base)     = make_float4(ko[0], ko[1], ko[2], ko[3]);
    *(float4*)(krow + base + 4) = make_float4(ko[4], ko[5], ko[6], ko[7]);
}

// ---------------------------------------------------------------------------
// Tensor-core flash attention, bf16 3-term (S and P·V), fp32 softmax.
// CTA: 128 q-rows, one (b,h). 8 warps (16 q-rows each). BKV=64.
// smem: Q hi/lo 64KB resident + double-buffered K/V hi/lo stages 2x64KB.
// ---------------------------------------------------------------------------
#define FATT_SMEM 196608
#define FCL2 (0.08838834764831845f * 1.4426950408889634f)   // (1/sqrt(128))*log2(e)

__global__ __launch_bounds__(256, 1)
void flashmma_kernel(const __nv_bfloat16* __restrict__ Qhi, const __nv_bfloat16* __restrict__ Qlo,
                     const __nv_bfloat16* __restrict__ Khi, const __nv_bfloat16* __restrict__ Klo,
                     const __nv_bfloat16* __restrict__ Vhi, const __nv_bfloat16* __restrict__ Vlo,
                     float* __restrict__ O)
{
    extern __shared__ __align__(1024) char smem[];
    const uint32_t sb   = smem_u32(smem);
    const int tid = threadIdx.x, wid = tid >> 5, lane = tid & 31;
    const int bh = blockIdx.y, b = bh >> 4, h = bh & 15;
    const int q0 = blockIdx.x * 128;
    const size_t rowbase = (size_t)b * SEQ;
    const int hoff = h * DHEAD;

    const uint32_t smQh = sb;
    const uint32_t smQl = sb + 32768;
    const uint32_t smKV = sb + 65536;

    // Q tiles (hi+lo): 4096 x 16B chunks
#pragma unroll
    for (int j = 0; j < 16; j++) {
        const int c = tid + j * 256;
        const int p = c >> 11, r = (c >> 4) & 127, ch = c & 15;
        const uint32_t dst = (p ? smQl : smQh) + SWZ(r, ch);
        const __nv_bfloat16* src = (p ? Qlo : Qhi)
            + (rowbase + q0 + r) * DIMV + hoff + ch * 8;
        CP_ASYNC16(dst, src);
    }
    auto load_kv = [&](int kv0, int buf) {
        const uint32_t bo = smKV + buf * 65536;
#pragma unroll
        for (int j = 0; j < 16; j++) {
            const int c = tid + j * 256;
            const int p = c >> 10, r = (c >> 4) & 63, ch = c & 15;
            const __nv_bfloat16* pl = (p == 0) ? Khi : (p == 1) ? Klo : (p == 2) ? Vhi : Vlo;
            const uint32_t dst = bo + p * 16384 + SWZ(r, ch);
            CP_ASYNC16(dst, pl + (rowbase + kv0 + r) * DIMV + hoff + ch * 8);
        }
    };
    load_kv(0, 0);
    CP_COMMIT();

    float co[16][4];
#pragma unroll
    for (int j = 0; j < 16; j++)
#pragma unroll
        for (int t = 0; t < 4; t++) co[j][t] = 0.f;
    float m0p = -1e30f, m1p = -1e30f, l0 = 0.f, l1 = 0.f;

    const int a_rl  = wid * 16 + (lane & 15);          // Q ldsm row
    const int a_chx = lane >> 4;
    const int b_rl  = ((lane >> 4) << 3) + (lane & 7); // K ldsm row-in-tile
    const int b_chx = (lane >> 3) & 1;
    const int v_rl  = lane & 15;                       // V ldsm row-in-tile
    const int v_chx = lane >> 4;

    for (int s = 0; s < 32; s++) {
        const int buf = s & 1;
        if (s + 1 < 32) { load_kv((s + 1) * 64, buf ^ 1); CP_COMMIT(); CP_WAIT1(); }
        else            { CP_WAIT0(); }
        __syncthreads();

        const uint32_t Kh = smKV + buf * 65536;
        const uint32_t Kl = Kh + 16384;
        const uint32_t Vh = Kh + 32768;
        const uint32_t Vl = Kh + 49152;

        // ---- S = Q @ K^T (128x64 per CTA; warp: 16x64) ----
        float cs[8][4];
#pragma unroll
        for (int j = 0; j < 8; j++)
#pragma unroll
            for (int t = 0; t < 4; t++) cs[j][t] = 0.f;

#pragma unroll
        for (int kk = 0; kk < 8; kk++) {
            uint32_t qh[4], ql[4], kh[8][2], kl[8][2];
            const uint32_t qa = SWZ(a_rl, 2 * kk + a_chx);
            ldsm4(qh, smQh + qa);
            ldsm4(ql, smQl + qa);
#pragma unroll
            for (int jj = 0; jj < 4; jj++) {
                const uint32_t ka = SWZ(16 * jj + b_rl, 2 * kk + b_chx);
                uint32_t t[4];
                ldsm4(t, Kh + ka);
                kh[2*jj][0] = t[0];   kh[2*jj][1] = t[1];
                kh[2*jj+1][0] = t[2]; kh[2*jj+1][1] = t[3];
                ldsm4(t, Kl + ka);
                kl[2*jj][0] = t[0];   kl[2*jj][1] = t[1];
                kl[2*jj+1][0] = t[2]; kl[2*jj+1][1] = t[3];
            }
#pragma unroll
            for (int j = 0; j < 8; j++) {
                mma16816(cs[j], qh, kh[j]);
                mma16816(cs[j], qh, kl[j]);
                mma16816(cs[j], ql, kh[j]);
            }
        }

        // ---- online softmax (rows r = lane>>2 and r+8; 4-lane groups) ----
        float mx0 = -1e30f, mx1 = -1e30f;
#pragma unroll
        for (int j = 0; j < 8; j++) {
            mx0 = fmaxf(mx0, fmaxf(cs[j][0], cs[j][1]));
            mx1 = fmaxf(mx1, fmaxf(cs[j][2], cs[j][3]));
        }
        mx0 = fmaxf(mx0, __shfl_xor_sync(0xffffffffu, mx0, 1));
        mx0 = fmaxf(mx0, __shfl_xor_sync(0xffffffffu, mx0, 2));
        mx1 = fmaxf(mx1, __shfl_xor_sync(0xffffffffu, mx1, 1));
        mx1 = fmaxf(mx1, __shfl_xor_sync(0xffffffffu, mx1, 2));
        const float mn0 = fmaxf(m0p, mx0);
        const float mn1 = fmaxf(m1p, mx1);
        float s0 = 0.f, s1 = 0.f;
#pragma unroll
        for (int j = 0; j < 8; j++) {
            cs[j][0] = exp2f((cs[j][0] - mn0) * FCL2); s0 += cs[j][0];
            cs[j][1] = exp2f((cs[j][1] - mn0) * FCL2); s0 += cs[j][1];
            cs[j][2] = exp2f((cs[j][2] - mn1) * FCL2); s1 += cs[j][2];
            cs[j][3] = exp2f((cs[j][3] - mn1) * FCL2); s1 += cs[j][3];
        }
        s0 += __shfl_xor_sync(0xffffffffu, s0, 1);
        s0 += __shfl_xor_sync(0xffffffffu, s0, 2);
        s1 += __shfl_xor_sync(0xffffffffu, s1, 1);
        s1 += __shfl_xor_sync(0xffffffffu, s1, 2);
        const float al0 = exp2f((m0p - mn0) * FCL2);
        const float al1 = exp2f((m1p - mn1) * FCL2);
        l0 = l0 * al0 + s0;  l1 = l1 * al1 + s1;
        m0p = mn0;  m1p = mn1;
#pragma unroll
        for (int j = 0; j < 16; j++) {
            co[j][0] *= al0; co[j][1] *= al0;
            co[j][2] *= al1; co[j][3] *= al1;
        }

        // ---- O += P @ V (P frags from S accum, split hi/lo in-register) ----
#pragma unroll
        for (int t = 0; t < 4; t++) {
            uint32_t ph[4], pl4[4];
            psplit(cs[2*t][0],   cs[2*t][1],   ph[0], pl4[0]);
            psplit(cs[2*t][2],   cs[2*t][3],   ph[1], pl4[1]);
            psplit(cs[2*t+1][0], cs[2*t+1][1], ph[2], pl4[2]);
            psplit(cs[2*t+1][2], cs[2*t+1][3], ph[3], pl4[3]);
#pragma unroll
            for (int jp = 0; jp < 8; jp++) {
                const uint32_t va = SWZ(16 * t + v_rl, 2 * jp + v_chx);
                uint32_t th[4], tl[4];
                ldsm4t(th, Vh + va);
                ldsm4t(tl, Vl + va);
                mma16816(co[2*jp],   ph,  th);
                mma16816(co[2*jp+1], ph,  th + 2);
                mma16816(co[2*jp],   ph,  tl);
                mma16816(co[2*jp+1], ph,  tl + 2);
                mma16816(co[2*jp],   pl4, th);
                mma16816(co[2*jp+1], pl4, th + 2);
            }
        }
        __syncthreads();
    }

    // ---- epilogue: O / l, write fp32 [b,s,h*128+d] ----
    const float i0 = 1.f / l0, i1 = 1.f / l1;
    float* o0 = O + (rowbase + q0 + wid * 16 + (lane >> 2)) * DIMV + hoff + 2 * (lane & 3);
    float* o1 = o0 + 8 * DIMV;
#pragma unroll
    for (int j = 0; j < 16; j++) {
        *(float2*)(o0 + 8 * j) = make_float2(co[j][0] * i0, co[j][1] * i0);
        *(float2*)(o1 + 8 * j) = make_float2(co[j][2] * i1, co[j][3] * i1);
    }
}

// ---------------------------------------------------------------------------
extern "C" void kernel_launch(void* const* d_in, const int* in_sizes, int n_in,
                              void* d_out, int out_size)
{
    const float* hs  = (const float*)d_in[0];
    const float* rot = (const float*)d_in[1];
    const float* Wq  = (const float*)d_in[2];
    const float* bq  = (const float*)d_in[3];
    const float* Wk  = (const float*)d_in[4];
    const float* bk  = (const float*)d_in[5];
    const float* Wv  = (const float*)d_in[6];
    const float* bv  = (const float*)d_in[7];
    const float* nqw = (const float*)d_in[8];
    const float* nkw = (const float*)d_in[9];
    const float* hks = (const float*)d_in[10];
    const float* Wo  = (const float*)d_in[11];
    const float* bo  = (const float*)d_in[12];
    const int*   ocl = (const int*)d_in[13];
    float* out = (float*)d_out;

    float *qp, *kp, *vp, *ap;
    cudaGetSymbolAddress((void**)&qp, g_q);
    cudaGetSymbolAddress((void**)&kp, g_k);
    cudaGetSymbolAddress((void**)&vp, g_v);
    cudaGetSymbolAddress((void**)&ap, g_attn);

    __nv_bfloat16 *ahi, *alo, *khi, *klo, *vhi, *vlo;
    __nv_bfloat16 *wqh, *wql, *wkh, *wkl, *wvh, *wvl, *woh, *wol;
    cudaGetSymbolAddress((void**)&ahi, g_ahi);
    cudaGetSymbolAddress((void**)&alo, g_alo);
    cudaGetSymbolAddress((void**)&khi, g_khi);
    cudaGetSymbolAddress((void**)&klo, g_klo);
    cudaGetSymbolAddress((void**)&vhi, g_vhi);
    cudaGetSymbolAddress((void**)&vlo, g_vlo);
    cudaGetSymbolAddress((void**)&wqh, g_wqhi);
    cudaGetSymbolAddress((void**)&wql, g_wqlo);
    cudaGetSymbolAddress((void**)&wkh, g_wkhi);
    cudaGetSymbolAddress((void**)&wkl, g_wklo);
    cudaGetSymbolAddress((void**)&wvh, g_wvhi);
    cudaGetSymbolAddress((void**)&wvl, g_wvlo);
    cudaGetSymbolAddress((void**)&woh, g_wohi);
    cudaGetSymbolAddress((void**)&wol, g_wolo);

    const int nAct = MROWS * DIMV;       // 8.4M
    const int nW   = DIMV * DIMV;        // 4.2M

    split_kernel<<<nAct / 1024, 256>>>(hs, ahi, alo, nAct);
    split_kernel<<<nW / 1024, 256>>>(Wq, wqh, wql, nW);
    split_kernel<<<nW / 1024, 256>>>(Wk, wkh, wkl, nW);
    split_kernel<<<nW / 1024, 256>>>(Wv, wvh, wvl, nW);
    split_kernel<<<nW / 1024, 256>>>(Wo, woh, wol, nW);

    cudaFuncSetAttribute(gemm_mma_kernel,
                         cudaFuncAttributeMaxDynamicSharedMemorySize, GEMM_SMEM);
    dim3 gg(DIMV / 256, MROWS / 128);   // (8, 32)
    gemm_mma_kernel<<<gg, 256, GEMM_SMEM>>>(ahi, alo, wqh, wql, bq, qp);
    gemm_mma_kernel<<<gg, 256, GEMM_SMEM>>>(ahi, alo, wkh, wkl, bk, kp);
    gemm_mma_kernel<<<gg, 256, GEMM_SMEM>>>(ahi, alo, wvh, wvl, bv, vp);

    normrope_kernel<<<MROWS, 256>>>(qp, kp, rot, nqw, nkw, hks, ocl);

    // splits for tensor-core attention (Q reuses activation-split buffers)
    split_kernel<<<nAct / 1024, 256>>>(qp, ahi, alo, nAct);
    split_kernel<<<nAct / 1024, 256>>>(kp, khi, klo, nAct);
    split_kernel<<<nAct / 1024, 256>>>(vp, vhi, vlo, nAct);

    cudaFuncSetAttribute(flashmma_kernel,
                         cudaFuncAttributeMaxDynamicSharedMemorySize, FATT_SMEM);
    flashmma_kernel<<<dim3(SEQ / 128, BATCH * HEADS), 256, FATT_SMEM>>>(
        ahi, alo, khi, klo, vhi, vlo, ap);

    split_kernel<<<nAct / 1024, 256>>>(ap, ahi, alo, nAct);
    gemm_mma_kernel<<<gg, 256, GEMM_SMEM>>>(ahi, alo, woh, wol, bo, out);
}